// round 14
// baseline (speedup 1.0000x reference)
#include <cuda_runtime.h>

#define HH 384
#define WW 384
#define HO 382
#define WO 382
#define RPAD 4
#define TH 18    /* rows staged: 8 + 2 + 2*RPAD */
#define TW 42    /* 32 + 2 + 2*RPAD */
#define TP 17    /* row-pair rows: TH-1 */

typedef unsigned long long u64;

// Constant layout (floats):
// [0,540)    cwp[27][20]: conv weight pairs, cwp[jj*20+2p] = (w[2p][jj], w[2p+1][jj])
// [540,558)  conv-bias pairs at 540+2p
// [560,668)  dcn packed per tap k (12-float stride):
//            +0,1 o0 pair (c0,c1), +2,3 o1 pair, +4,5 o2 pair,
//            +6,7,8 c2 weights (o0,o1,o2), +9..11 pad
// [668,671)  dcn bias
__constant__ __align__(16) float CW[672];
__device__ __align__(16) float d_scratch[672];

__device__ __forceinline__ u64 ffma2(u64 a, u64 b, u64 c){
    u64 d; asm("fma.rn.f32x2 %0,%1,%2,%3;" : "=l"(d) : "l"(a), "l"(b), "l"(c)); return d;
}
__device__ __forceinline__ u64 add2(u64 a, u64 b){
    u64 d; asm("add.rn.f32x2 %0,%1,%2;" : "=l"(d) : "l"(a), "l"(b)); return d;
}
__device__ __forceinline__ u64 sub2(u64 a, u64 b){
    u64 d; asm("sub.rn.f32x2 %0,%1,%2;" : "=l"(d) : "l"(a), "l"(b)); return d;
}
__device__ __forceinline__ u64 rep2(float x){
    u64 r; asm("mov.b64 %0,{%1,%1};" : "=l"(r) : "f"(x)); return r;
}
__device__ __forceinline__ u64 pack2(float a, float b){
    u64 r; asm("mov.b64 %0,{%1,%2};" : "=l"(r) : "f"(a), "f"(b)); return r;
}
__device__ __forceinline__ float2 unpack2(u64 v){
    float2 f; asm("mov.b64 {%0,%1},%2;" : "=f"(f.x), "=f"(f.y) : "l"(v)); return f;
}
__device__ __forceinline__ u64 ldc64(int foff){
    return *reinterpret_cast<const u64*>(&CW[foff]);
}
__device__ __forceinline__ ulonglong2 ldc128(int foff){
    return *reinterpret_cast<const ulonglong2*>(&CW[foff]);
}

__global__ void repack(const float* __restrict__ cw, const float* __restrict__ cb,
                       const float* __restrict__ dw, const float* __restrict__ db,
                       float* __restrict__ s)
{
    int t = threadIdx.x;
    if (t < 486) { int o = t / 27, jj = t % 27; s[jj * 20 + o] = cw[t]; }
    else if (t < 504) { s[540 + (t - 486)] = cb[t - 486]; }
    else if (t < 531) {
        int i = t - 504; int o = i / 9, k = i % 9;
        s[560 + k * 12 + 2 * o + 0] = dw[o * 27 + 0 + k];
        s[560 + k * 12 + 2 * o + 1] = dw[o * 27 + 9 + k];
        s[560 + k * 12 + 6 + o]     = dw[o * 27 + 18 + k];
    }
    else if (t < 534) { s[668 + (t - 531)] = db[t - 531]; }
    else if (t < 543) {
        int k = t - 534;
        s[560 + k * 12 + 9] = 0.f; s[560 + k * 12 + 10] = 0.f; s[560 + k * 12 + 11] = 0.f;
    }
}

// Fused offset-conv + deformable conv. Block = 32x4 threads, 2 vertically
// adjacent pixels per thread (serial A-then-B deform).
// ROW-PAIR DUPLICATED tile: tPD[r][q] holds (c0,c1) for rows r AND r+1, so a
// bilinear tap needs 2 LDS.128 + 2 LDS.64 (4 loads) instead of 8 — the
// gather wavefront count (the R13 bottleneck) drops ~33%.
// Zero-padded outside the image => maskless lerp bilinear; window-clamped.
__global__ __launch_bounds__(128, 6) void dcn_fused(
    const float* __restrict__ x, float* __restrict__ out)
{
    __shared__ ulonglong2 tPD[TP][TW];   // 11424 B  ((c0,c1)@r, (c0,c1)@r+1)
    __shared__ float2     t2D[TP][TW];   //  5712 B  (c2@r, c2@r+1)

    const int tx = threadIdx.x, ty = threadIdx.y;
    const int tid = ty * 32 + tx;
    const int i0 = blockIdx.y * 8, j0 = blockIdx.x * 32, b = blockIdx.z;
    const int ybase = i0 - RPAD, xbase = j0 - RPAD;

    {
        const float* p0 = x + (size_t)b * 3 * HH * WW;
        const float* p1 = p0 + HH * WW;
        const float* p2 = p1 + HH * WW;
        // ---- Stage tile, ZERO outside image; each row written to both pair slots ----
        #pragma unroll
        for (int it = 0; it < 6; it++) {
            int idx = tid + it * 128;
            if (idx < TH * TW) {
                int r = idx / TW, q = idx % TW;
                int gy = ybase + r, gx = xbase + q;
                bool vin = ((unsigned)gy < (unsigned)HH) & ((unsigned)gx < (unsigned)WW);
                int g = min(max(gy, 0), HH - 1) * WW + min(max(gx, 0), WW - 1);
                float m = vin ? 1.f : 0.f;
                float v0 = __ldg(p0 + g) * m, v1 = __ldg(p1 + g) * m, v2 = __ldg(p2 + g) * m;
                u64 v01 = pack2(v0, v1);
                if (r < TP) { tPD[r][q].x = v01; t2D[r][q].x = v2; }        // row r of pair r
                if (r >= 1) { tPD[r - 1][q].y = v01; t2D[r - 1][q].y = v2; } // row r of pair r-1
            }
        }
    }
    __syncthreads();

    const int j  = j0 + tx;
    const int iA = i0 + 2 * ty;            // even; iB = iA+1. Both valid or both not.
    if (j >= WO || iA >= HO) return;

    // ---- Offset conv for both pixels; weights loaded once, taps via row pairs ----
    u64 offA[9], offB[9];
    #pragma unroll
    for (int p = 0; p < 9; p++) { u64 bp = ldc64(540 + 2 * p); offA[p] = bp; offB[p] = bp; }

    const int lyA = 2 * ty + RPAD, lx = tx + RPAD;

    #pragma unroll
    for (int kx = 0; kx < 3; kx++) {
        // 4 consecutive rows via 2 pair loads
        ulonglong2 pa_ = tPD[lyA][lx + kx];       // rows lyA, lyA+1
        ulonglong2 pb_ = tPD[lyA + 2][lx + kx];   // rows lyA+2, lyA+3
        float2 qa_ = t2D[lyA][lx + kx];
        float2 qb_ = t2D[lyA + 2][lx + kx];
        u64 rp[4] = { pa_.x, pa_.y, pb_.x, pb_.y };
        float r2[4] = { qa_.x, qa_.y, qb_.x, qb_.y };
        #pragma unroll
        for (int ky = 0; ky < 3; ky++) {
            float2 fA = unpack2(rp[ky]);
            float2 fB = unpack2(rp[ky + 1]);
            #pragma unroll
            for (int c = 0; c < 3; c++) {
                const int jj = c * 9 + ky * 3 + kx;
                float xa = (c == 0) ? fA.x : (c == 1) ? fA.y : r2[ky];
                float xb = (c == 0) ? fB.x : (c == 1) ? fB.y : r2[ky + 1];
                u64 xa2 = rep2(xa), xb2 = rep2(xb);
                ulonglong2 v0 = ldc128(jj * 20 + 0);
                ulonglong2 v1 = ldc128(jj * 20 + 4);
                ulonglong2 v2 = ldc128(jj * 20 + 8);
                ulonglong2 v3 = ldc128(jj * 20 + 12);
                u64 p8 = ldc64(jj * 20 + 16);
                offA[0] = ffma2(xa2, v0.x, offA[0]); offB[0] = ffma2(xb2, v0.x, offB[0]);
                offA[1] = ffma2(xa2, v0.y, offA[1]); offB[1] = ffma2(xb2, v0.y, offB[1]);
                offA[2] = ffma2(xa2, v1.x, offA[2]); offB[2] = ffma2(xb2, v1.x, offB[2]);
                offA[3] = ffma2(xa2, v1.y, offA[3]); offB[3] = ffma2(xb2, v1.y, offB[3]);
                offA[4] = ffma2(xa2, v2.x, offA[4]); offB[4] = ffma2(xb2, v2.x, offB[4]);
                offA[5] = ffma2(xa2, v2.y, offA[5]); offB[5] = ffma2(xb2, v2.y, offB[5]);
                offA[6] = ffma2(xa2, v3.x, offA[6]); offB[6] = ffma2(xb2, v3.x, offB[6]);
                offA[7] = ffma2(xa2, v3.y, offA[7]); offB[7] = ffma2(xb2, v3.y, offB[7]);
                offA[8] = ffma2(xa2, p8,   offA[8]); offB[8] = ffma2(xb2, p8,   offB[8]);
            }
        }
    }

    // ---- Deformable sampling + einsum (4-load taps via row pairs) ----
    const float fj = (float)j;
    auto deform = [&](const u64* off, float fi, float* res) {
        u64 accP0 = 0ULL, accP1 = 0ULL, accP2 = 0ULL;
        float a20 = 0.f, a21 = 0.f, a22 = 0.f;
        #pragma unroll
        for (int k = 0; k < 9; k++) {
            const int ky = k / 3, kx = k % 3;
            u64 pyx = add2(off[k], pack2(fi + (float)ky, fj + (float)kx));
            float2 q = unpack2(pyx);                      // (py, px)
            int y0 = __float2int_rd(q.x), x0 = __float2int_rd(q.y);
            float wy = q.x - (float)y0, wx = q.y - (float)x0;

            // Window-clamped pair coords (pair r covers rows r, r+1).
            int ry = min(max(y0 - ybase, 0), TP - 1);
            int rx = min(max(x0 - xbase, 0), TW - 2);

            ulonglong2 ga = tPD[ry][rx];        // g00 = ga.x, g10 = ga.y
            ulonglong2 gb = tPD[ry][rx + 1];    // g01 = gb.x, g11 = gb.y
            float2 sa = t2D[ry][rx];            // s00, s10
            float2 sb = t2D[ry][rx + 1];        // s01, s11

            u64 wx2 = rep2(wx), wy2 = rep2(wy);
            u64 r0 = ffma2(wx2, sub2(gb.x, ga.x), ga.x);
            u64 r1 = ffma2(wx2, sub2(gb.y, ga.y), ga.y);
            u64 v01 = ffma2(wy2, sub2(r1, r0), r0);
            float t0 = fmaf(wx, sb.x - sa.x, sa.x);
            float t1 = fmaf(wx, sb.y - sa.y, sa.y);
            float v2 = fmaf(wy, t1 - t0, t0);

            ulonglong2 wa = ldc128(560 + k * 12);       // (o0 pair, o1 pair)
            ulonglong2 wb = ldc128(560 + k * 12 + 4);   // (o2 pair, (c2_0,c2_1))
            float2 c2p = unpack2(wb.y);
            float c22 = CW[560 + k * 12 + 8];
            accP0 = ffma2(v01, wa.x, accP0);
            accP1 = ffma2(v01, wa.y, accP1);
            accP2 = ffma2(v01, wb.x, accP2);
            a20 = fmaf(v2, c2p.x, a20);
            a21 = fmaf(v2, c2p.y, a21);
            a22 = fmaf(v2, c22, a22);
        }
        float2 r0 = unpack2(accP0), r1 = unpack2(accP1), r2 = unpack2(accP2);
        res[0] = r0.x + r0.y + a20 + CW[668];
        res[1] = r1.x + r1.y + a21 + CW[669];
        res[2] = r2.x + r2.y + a22 + CW[670];
    };

    float rA[3], rB[3];
    deform(offA, (float)iA,        rA);
    deform(offB, (float)iA + 1.f,  rB);

    const size_t plane = (size_t)HO * WO;
    size_t pa = (size_t)b * 3 * plane + (size_t)iA * WO + j;
    out[pa]             = rA[0];
    out[pa + plane]     = rA[1];
    out[pa + 2 * plane] = rA[2];
    pa += WO;
    out[pa]             = rB[0];
    out[pa + plane]     = rB[1];
    out[pa + 2 * plane] = rB[2];
}

extern "C" void kernel_launch(void* const* d_in, const int* in_sizes, int n_in,
                              void* d_out, int out_size)
{
    const float* x      = (const float*)d_in[0];
    const float* conv_w = (const float*)d_in[1];
    const float* conv_b = (const float*)d_in[2];
    const float* dcn_w  = (const float*)d_in[3];
    const float* dcn_b  = (const float*)d_in[4];
    float* out = (float*)d_out;

    float* sp = nullptr;  void* cp = nullptr;
    cudaGetSymbolAddress((void**)&sp, d_scratch);
    cudaGetSymbolAddress(&cp, CW);

    repack<<<1, 544>>>(conv_w, conv_b, dcn_w, dcn_b, sp);
    cudaMemcpyAsync(cp, sp, 672 * sizeof(float), cudaMemcpyDeviceToDevice);

    dim3 blk(32, 4);
    dim3 grd((WO + 31) / 32, (HO + 7) / 8, 16);
    dcn_fused<<<grd, blk>>>(x, out);
}

// round 15
// speedup vs baseline: 1.5951x; 1.5951x over previous
#include <cuda_runtime.h>

#define HH 384
#define WW 384
#define HO 382
#define WO 382
#define RPAD 4
#define TH 18    /* 8 + 2 + 2*RPAD */
#define TW 42    /* 32 + 2 + 2*RPAD */

typedef unsigned long long u64;

// Constant layout (floats):
// [0,540)    cwp[27][20]: conv weight pairs, cwp[jj*20+2p] = (w[2p][jj], w[2p+1][jj])
// [540,558)  conv-bias pairs at 540+2p
// [560,668)  dcn packed per tap k (12-float stride):
//            +0,1 o0 pair (c0,c1), +2,3 o1 pair, +4,5 o2 pair,
//            +6,7,8 c2 weights (o0,o1,o2), +9..11 pad
// [668,671)  dcn bias
__constant__ __align__(16) float CW[672];
__device__ __align__(16) float d_scratch[672];

__device__ __forceinline__ u64 ffma2(u64 a, u64 b, u64 c){
    u64 d; asm("fma.rn.f32x2 %0,%1,%2,%3;" : "=l"(d) : "l"(a), "l"(b), "l"(c)); return d;
}
__device__ __forceinline__ u64 add2(u64 a, u64 b){
    u64 d; asm("add.rn.f32x2 %0,%1,%2;" : "=l"(d) : "l"(a), "l"(b)); return d;
}
__device__ __forceinline__ u64 sub2(u64 a, u64 b){
    u64 d; asm("sub.rn.f32x2 %0,%1,%2;" : "=l"(d) : "l"(a), "l"(b)); return d;
}
__device__ __forceinline__ u64 rep2(float x){
    u64 r; asm("mov.b64 %0,{%1,%1};" : "=l"(r) : "f"(x)); return r;
}
__device__ __forceinline__ u64 pack2(float a, float b){
    u64 r; asm("mov.b64 %0,{%1,%2};" : "=l"(r) : "f"(a), "f"(b)); return r;
}
__device__ __forceinline__ float2 unpack2(u64 v){
    float2 f; asm("mov.b64 {%0,%1},%2;" : "=f"(f.x), "=f"(f.y) : "l"(v)); return f;
}
__device__ __forceinline__ u64 ldc64(int foff){
    return *reinterpret_cast<const u64*>(&CW[foff]);
}
__device__ __forceinline__ ulonglong2 ldc128(int foff){
    return *reinterpret_cast<const ulonglong2*>(&CW[foff]);
}

__global__ void repack(const float* __restrict__ cw, const float* __restrict__ cb,
                       const float* __restrict__ dw, const float* __restrict__ db,
                       float* __restrict__ s)
{
    int t = threadIdx.x;
    if (t < 486) { int o = t / 27, jj = t % 27; s[jj * 20 + o] = cw[t]; }
    else if (t < 504) { s[540 + (t - 486)] = cb[t - 486]; }
    else if (t < 531) {
        int i = t - 504; int o = i / 9, k = i % 9;
        s[560 + k * 12 + 2 * o + 0] = dw[o * 27 + 0 + k];
        s[560 + k * 12 + 2 * o + 1] = dw[o * 27 + 9 + k];
        s[560 + k * 12 + 6 + o]     = dw[o * 27 + 18 + k];
    }
    else if (t < 534) { s[668 + (t - 531)] = db[t - 531]; }
    else if (t < 543) {
        int k = t - 534;
        s[560 + k * 12 + 9] = 0.f; s[560 + k * 12 + 10] = 0.f; s[560 + k * 12 + 11] = 0.f;
    }
}

// Fused offset-conv + deformable conv. R13 schedule (serial A-then-B deform,
// zero-padded maskless lerp, window clamp). ONE change: c2 channel stored as
// COLUMN-PAIR duplicates t2c[r][q] = (c2[r][q], c2[r][q+1]) so each bilinear
// tap needs 2 LDS.64 for c2 instead of 4 LDS.32. All smem loads stay <= 64-bit.
__global__ __launch_bounds__(128, 6) void dcn_fused(
    const float* __restrict__ x, float* __restrict__ out)
{
    __shared__ u64    tileP[TH][TW];   // 6048 B  (c0,c1) pairs
    __shared__ float2 t2c[TH][TW];     // 6048 B  (c2[q], c2[q+1])

    const int tx = threadIdx.x, ty = threadIdx.y;
    const int tid = ty * 32 + tx;
    const int i0 = blockIdx.y * 8, j0 = blockIdx.x * 32, b = blockIdx.z;
    const int ybase = i0 - RPAD, xbase = j0 - RPAD;

    {
        const float* p0 = x + (size_t)b * 3 * HH * WW;
        const float* p1 = p0 + HH * WW;
        const float* p2 = p1 + HH * WW;
        // ---- Stage tile, ZERO outside image. c2 written into both pair slots ----
        #pragma unroll
        for (int it = 0; it < 6; it++) {
            int idx = tid + it * 128;
            if (idx < TH * TW) {
                int r = idx / TW, q = idx % TW;
                int gy = ybase + r, gx = xbase + q;
                bool vin = ((unsigned)gy < (unsigned)HH) & ((unsigned)gx < (unsigned)WW);
                int g = min(max(gy, 0), HH - 1) * WW + min(max(gx, 0), WW - 1);
                float m = vin ? 1.f : 0.f;
                tileP[r][q] = pack2(__ldg(p0 + g) * m, __ldg(p1 + g) * m);
                float v2 = __ldg(p2 + g) * m;
                t2c[r][q].x = v2;                    // (q, q+1) pair slot .x
                if (q >= 1) t2c[r][q - 1].y = v2;    // previous pair's .y
                else        t2c[r][TW - 1].y = 0.f;  // never read; keep defined
            }
        }
    }
    __syncthreads();

    const int j  = j0 + tx;
    const int iA = i0 + 2 * ty;            // even; iB = iA+1. Both valid or both not.
    if (j >= WO || iA >= HO) return;

    // ---- Offset conv for both pixels; each weight vector loaded ONCE ----
    u64 offA[9], offB[9];
    #pragma unroll
    for (int p = 0; p < 9; p++) { u64 bp = ldc64(540 + 2 * p); offA[p] = bp; offB[p] = bp; }

    const int lyA = 2 * ty + RPAD, lx = tx + RPAD;

    #pragma unroll
    for (int kx = 0; kx < 3; kx++) {
        u64 rp[4]; float r2[4];
        #pragma unroll
        for (int r = 0; r < 4; r++) {
            rp[r] = tileP[lyA + r][lx + kx];
            r2[r] = t2c[lyA + r][lx + kx].x;
        }
        #pragma unroll
        for (int ky = 0; ky < 3; ky++) {
            float2 fA = unpack2(rp[ky]);
            float2 fB = unpack2(rp[ky + 1]);
            #pragma unroll
            for (int c = 0; c < 3; c++) {
                const int jj = c * 9 + ky * 3 + kx;
                float xa = (c == 0) ? fA.x : (c == 1) ? fA.y : r2[ky];
                float xb = (c == 0) ? fB.x : (c == 1) ? fB.y : r2[ky + 1];
                u64 xa2 = rep2(xa), xb2 = rep2(xb);
                ulonglong2 v0 = ldc128(jj * 20 + 0);
                ulonglong2 v1 = ldc128(jj * 20 + 4);
                ulonglong2 v2 = ldc128(jj * 20 + 8);
                ulonglong2 v3 = ldc128(jj * 20 + 12);
                u64 p8 = ldc64(jj * 20 + 16);
                offA[0] = ffma2(xa2, v0.x, offA[0]); offB[0] = ffma2(xb2, v0.x, offB[0]);
                offA[1] = ffma2(xa2, v0.y, offA[1]); offB[1] = ffma2(xb2, v0.y, offB[1]);
                offA[2] = ffma2(xa2, v1.x, offA[2]); offB[2] = ffma2(xb2, v1.x, offB[2]);
                offA[3] = ffma2(xa2, v1.y, offA[3]); offB[3] = ffma2(xb2, v1.y, offB[3]);
                offA[4] = ffma2(xa2, v2.x, offA[4]); offB[4] = ffma2(xb2, v2.x, offB[4]);
                offA[5] = ffma2(xa2, v2.y, offA[5]); offB[5] = ffma2(xb2, v2.y, offB[5]);
                offA[6] = ffma2(xa2, v3.x, offA[6]); offB[6] = ffma2(xb2, v3.x, offB[6]);
                offA[7] = ffma2(xa2, v3.y, offA[7]); offB[7] = ffma2(xb2, v3.y, offB[7]);
                offA[8] = ffma2(xa2, p8,   offA[8]); offB[8] = ffma2(xb2, p8,   offB[8]);
            }
        }
    }

    // ---- Deformable sampling + einsum (clamped lerp; c2 via column pairs) ----
    const float fj = (float)j;
    auto deform = [&](const u64* off, float fi, float* res) {
        u64 accP0 = 0ULL, accP1 = 0ULL, accP2 = 0ULL;
        float a20 = 0.f, a21 = 0.f, a22 = 0.f;
        #pragma unroll
        for (int k = 0; k < 9; k++) {
            const int ky = k / 3, kx = k % 3;
            u64 pyx = add2(off[k], pack2(fi + (float)ky, fj + (float)kx));
            float2 q = unpack2(pyx);                      // (py, px)
            int y0 = __float2int_rd(q.x), x0 = __float2int_rd(q.y);
            float wy = q.x - (float)y0, wx = q.y - (float)x0;

            // Window-clamped tile coords (no fallback path).
            int ry = min(max(y0 - ybase, 0), TH - 2);
            int rx = min(max(x0 - xbase, 0), TW - 2);

            u64 wx2 = rep2(wx), wy2 = rep2(wy);
            u64 g00 = tileP[ry][rx],     g01 = tileP[ry][rx + 1];
            u64 g10 = tileP[ry + 1][rx], g11 = tileP[ry + 1][rx + 1];
            u64 r0 = ffma2(wx2, sub2(g01, g00), g00);
            u64 r1 = ffma2(wx2, sub2(g11, g10), g10);
            u64 v01 = ffma2(wy2, sub2(r1, r0), r0);
            float2 sa = t2c[ry][rx];          // (s00, s01)
            float2 sb = t2c[ry + 1][rx];      // (s10, s11)
            float t0 = fmaf(wx, sa.y - sa.x, sa.x);
            float t1 = fmaf(wx, sb.y - sb.x, sb.x);
            float v2 = fmaf(wy, t1 - t0, t0);

            ulonglong2 wa = ldc128(560 + k * 12);       // (o0 pair, o1 pair)
            ulonglong2 wb = ldc128(560 + k * 12 + 4);   // (o2 pair, (c2_0,c2_1))
            float2 c2p = unpack2(wb.y);
            float c22 = CW[560 + k * 12 + 8];
            accP0 = ffma2(v01, wa.x, accP0);
            accP1 = ffma2(v01, wa.y, accP1);
            accP2 = ffma2(v01, wb.x, accP2);
            a20 = fmaf(v2, c2p.x, a20);
            a21 = fmaf(v2, c2p.y, a21);
            a22 = fmaf(v2, c22, a22);
        }
        float2 r0 = unpack2(accP0), r1 = unpack2(accP1), r2 = unpack2(accP2);
        res[0] = r0.x + r0.y + a20 + CW[668];
        res[1] = r1.x + r1.y + a21 + CW[669];
        res[2] = r2.x + r2.y + a22 + CW[670];
    };

    float rA[3], rB[3];
    deform(offA, (float)iA,        rA);
    deform(offB, (float)iA + 1.f,  rB);

    const size_t plane = (size_t)HO * WO;
    size_t pa = (size_t)b * 3 * plane + (size_t)iA * WO + j;
    out[pa]             = rA[0];
    out[pa + plane]     = rA[1];
    out[pa + 2 * plane] = rA[2];
    pa += WO;
    out[pa]             = rB[0];
    out[pa + plane]     = rB[1];
    out[pa + 2 * plane] = rB[2];
}

extern "C" void kernel_launch(void* const* d_in, const int* in_sizes, int n_in,
                              void* d_out, int out_size)
{
    const float* x      = (const float*)d_in[0];
    const float* conv_w = (const float*)d_in[1];
    const float* conv_b = (const float*)d_in[2];
    const float* dcn_w  = (const float*)d_in[3];
    const float* dcn_b  = (const float*)d_in[4];
    float* out = (float*)d_out;

    float* sp = nullptr;  void* cp = nullptr;
    cudaGetSymbolAddress((void**)&sp, d_scratch);
    cudaGetSymbolAddress(&cp, CW);

    repack<<<1, 544>>>(conv_w, conv_b, dcn_w, dcn_b, sp);
    cudaMemcpyAsync(cp, sp, 672 * sizeof(float), cudaMemcpyDeviceToDevice);

    dim3 blk(32, 4);
    dim3 grd((WO + 31) / 32, (HO + 7) / 8, 16);
    dcn_fused<<<grd, blk>>>(x, out);
}

// round 16
// speedup vs baseline: 1.6978x; 1.0644x over previous
#include <cuda_runtime.h>

#define HH 384
#define WW 384
#define HO 382
#define WO 382
#define RPAD 3
#define TH 16    /* 8 + 2 + 2*RPAD */
#define TW 40    /* 32 + 2 + 2*RPAD */

typedef unsigned long long u64;

// Constant layout (floats):
// [0,540)    cwp[27][20]: conv weight pairs, cwp[jj*20+2p] = (w[2p][jj], w[2p+1][jj])
// [540,558)  conv-bias pairs at 540+2p, PRE-OFFSET by the tap coords:
//            (bias_dy[k] + k/3, bias_dx[k] + k%3) for k = p
// [560,668)  dcn packed per tap k (12-float stride):
//            +0,1 o0 pair (c0,c1), +2,3 o1 pair, +4,5 o2 pair,
//            +6,7,8 c2 weights (o0,o1,o2), +9..11 pad
// [668,671)  dcn bias
__constant__ __align__(16) float CW[672];
__device__ __align__(16) float d_scratch[672];

__device__ __forceinline__ u64 ffma2(u64 a, u64 b, u64 c){
    u64 d; asm("fma.rn.f32x2 %0,%1,%2,%3;" : "=l"(d) : "l"(a), "l"(b), "l"(c)); return d;
}
__device__ __forceinline__ u64 add2(u64 a, u64 b){
    u64 d; asm("add.rn.f32x2 %0,%1,%2;" : "=l"(d) : "l"(a), "l"(b)); return d;
}
__device__ __forceinline__ u64 sub2(u64 a, u64 b){
    u64 d; asm("sub.rn.f32x2 %0,%1,%2;" : "=l"(d) : "l"(a), "l"(b)); return d;
}
__device__ __forceinline__ u64 rep2(float x){
    u64 r; asm("mov.b64 %0,{%1,%1};" : "=l"(r) : "f"(x)); return r;
}
__device__ __forceinline__ u64 pack2(float a, float b){
    u64 r; asm("mov.b64 %0,{%1,%2};" : "=l"(r) : "f"(a), "f"(b)); return r;
}
__device__ __forceinline__ float2 unpack2(u64 v){
    float2 f; asm("mov.b64 {%0,%1},%2;" : "=f"(f.x), "=f"(f.y) : "l"(v)); return f;
}
__device__ __forceinline__ u64 ldc64(int foff){
    return *reinterpret_cast<const u64*>(&CW[foff]);
}
__device__ __forceinline__ ulonglong2 ldc128(int foff){
    return *reinterpret_cast<const ulonglong2*>(&CW[foff]);
}

__global__ void repack(const float* __restrict__ cw, const float* __restrict__ cb,
                       const float* __restrict__ dw, const float* __restrict__ db,
                       float* __restrict__ s)
{
    int t = threadIdx.x;
    if (t < 486) { int o = t / 27, jj = t % 27; s[jj * 20 + o] = cw[t]; }
    else if (t < 504) {
        // bias pair element; fold the tap coordinate in: channel 2k -> +ky, 2k+1 -> +kx
        int e = t - 486;          // element index 0..17
        int k = e / 2;
        float addc = (e & 1) ? (float)(k % 3) : (float)(k / 3);
        s[540 + e] = cb[e] + addc;
    }
    else if (t < 531) {
        int i = t - 504; int o = i / 9, k = i % 9;
        s[560 + k * 12 + 2 * o + 0] = dw[o * 27 + 0 + k];
        s[560 + k * 12 + 2 * o + 1] = dw[o * 27 + 9 + k];
        s[560 + k * 12 + 6 + o]     = dw[o * 27 + 18 + k];
    }
    else if (t < 534) { s[668 + (t - 531)] = db[t - 531]; }
    else if (t < 543) {
        int k = t - 534;
        s[560 + k * 12 + 9] = 0.f; s[560 + k * 12 + 10] = 0.f; s[560 + k * 12 + 11] = 0.f;
    }
}

// Fused offset-conv + deformable conv (R13 schedule). Block = 32x4, 2 px/thread.
// Zero-padded tile => maskless lerp bilinear; out-of-window window-clamped.
// R16: tap coords folded into conv bias (pyx = off[k] + (fi,fj), base hoisted);
// RPAD=3 => 640-cell tile staged in exactly 5 full iterations.
__global__ __launch_bounds__(128, 6) void dcn_fused(
    const float* __restrict__ x, float* __restrict__ out)
{
    __shared__ u64   tileP[TH][TW];   // 5120 B  (c0,c1) pairs
    __shared__ float tile2[TH][TW];   // 2560 B  c2

    const int tx = threadIdx.x, ty = threadIdx.y;
    const int tid = ty * 32 + tx;
    const int i0 = blockIdx.y * 8, j0 = blockIdx.x * 32, b = blockIdx.z;
    const int ybase = i0 - RPAD, xbase = j0 - RPAD;

    {
        const float* p0 = x + (size_t)b * 3 * HH * WW;
        const float* p1 = p0 + HH * WW;
        const float* p2 = p1 + HH * WW;
        // ---- Stage tile, ZERO outside image. 640 = 5*128: no bounds check ----
        #pragma unroll
        for (int it = 0; it < 5; it++) {
            int idx = tid + it * 128;
            int r = idx / TW, q = idx % TW;
            int gy = ybase + r, gx = xbase + q;
            bool vin = ((unsigned)gy < (unsigned)HH) & ((unsigned)gx < (unsigned)WW);
            int g = min(max(gy, 0), HH - 1) * WW + min(max(gx, 0), WW - 1);
            float m = vin ? 1.f : 0.f;
            tileP[r][q] = pack2(__ldg(p0 + g) * m, __ldg(p1 + g) * m);
            tile2[r][q] = __ldg(p2 + g) * m;
        }
    }
    __syncthreads();

    const int j  = j0 + tx;
    const int iA = i0 + 2 * ty;            // even; iB = iA+1. Both valid or both not.
    if (j >= WO || iA >= HO) return;

    // ---- Offset conv for both pixels; each weight vector loaded ONCE ----
    // Bias pairs already include the tap coordinate (ky,kx).
    u64 offA[9], offB[9];
    #pragma unroll
    for (int p = 0; p < 9; p++) { u64 bp = ldc64(540 + 2 * p); offA[p] = bp; offB[p] = bp; }

    const int lyA = 2 * ty + RPAD, lx = tx + RPAD;

    #pragma unroll
    for (int kx = 0; kx < 3; kx++) {
        u64 rp[4]; float r2[4];
        #pragma unroll
        for (int r = 0; r < 4; r++) { rp[r] = tileP[lyA + r][lx + kx]; r2[r] = tile2[lyA + r][lx + kx]; }
        #pragma unroll
        for (int ky = 0; ky < 3; ky++) {
            float2 fA = unpack2(rp[ky]);
            float2 fB = unpack2(rp[ky + 1]);
            #pragma unroll
            for (int c = 0; c < 3; c++) {
                const int jj = c * 9 + ky * 3 + kx;
                float xa = (c == 0) ? fA.x : (c == 1) ? fA.y : r2[ky];
                float xb = (c == 0) ? fB.x : (c == 1) ? fB.y : r2[ky + 1];
                u64 xa2 = rep2(xa), xb2 = rep2(xb);
                ulonglong2 v0 = ldc128(jj * 20 + 0);
                ulonglong2 v1 = ldc128(jj * 20 + 4);
                ulonglong2 v2 = ldc128(jj * 20 + 8);
                ulonglong2 v3 = ldc128(jj * 20 + 12);
                u64 p8 = ldc64(jj * 20 + 16);
                offA[0] = ffma2(xa2, v0.x, offA[0]); offB[0] = ffma2(xb2, v0.x, offB[0]);
                offA[1] = ffma2(xa2, v0.y, offA[1]); offB[1] = ffma2(xb2, v0.y, offB[1]);
                offA[2] = ffma2(xa2, v1.x, offA[2]); offB[2] = ffma2(xb2, v1.x, offB[2]);
                offA[3] = ffma2(xa2, v1.y, offA[3]); offB[3] = ffma2(xb2, v1.y, offB[3]);
                offA[4] = ffma2(xa2, v2.x, offA[4]); offB[4] = ffma2(xb2, v2.x, offB[4]);
                offA[5] = ffma2(xa2, v2.y, offA[5]); offB[5] = ffma2(xb2, v2.y, offB[5]);
                offA[6] = ffma2(xa2, v3.x, offA[6]); offB[6] = ffma2(xb2, v3.x, offB[6]);
                offA[7] = ffma2(xa2, v3.y, offA[7]); offB[7] = ffma2(xb2, v3.y, offB[7]);
                offA[8] = ffma2(xa2, p8,   offA[8]); offB[8] = ffma2(xb2, p8,   offB[8]);
            }
        }
    }

    // ---- Deformable sampling + einsum (clamped lerp; base hoisted) ----
    const float fj = (float)j;
    auto deform = [&](const u64* off, float fi, float* res) {
        u64 accP0 = 0ULL, accP1 = 0ULL, accP2 = 0ULL;
        float a20 = 0.f, a21 = 0.f, a22 = 0.f;
        const u64 base = pack2(fi, fj);      // tap coords already in off[k]
        #pragma unroll
        for (int k = 0; k < 9; k++) {
            u64 pyx = add2(off[k], base);
            float2 q = unpack2(pyx);                      // (py, px)
            int y0 = __float2int_rd(q.x), x0 = __float2int_rd(q.y);
            float wy = q.x - (float)y0, wx = q.y - (float)x0;

            // Window-clamped tile coords (no fallback path).
            int ry = min(max(y0 - ybase, 0), TH - 2);
            int rx = min(max(x0 - xbase, 0), TW - 2);

            u64 wx2 = rep2(wx), wy2 = rep2(wy);
            u64 g00 = tileP[ry][rx],     g01 = tileP[ry][rx + 1];
            u64 g10 = tileP[ry + 1][rx], g11 = tileP[ry + 1][rx + 1];
            u64 r0 = ffma2(wx2, sub2(g01, g00), g00);
            u64 r1 = ffma2(wx2, sub2(g11, g10), g10);
            u64 v01 = ffma2(wy2, sub2(r1, r0), r0);
            float s00 = tile2[ry][rx],     s01 = tile2[ry][rx + 1];
            float s10 = tile2[ry + 1][rx], s11 = tile2[ry + 1][rx + 1];
            float t0 = fmaf(wx, s01 - s00, s00);
            float t1 = fmaf(wx, s11 - s10, s10);
            float v2 = fmaf(wy, t1 - t0, t0);

            ulonglong2 wa = ldc128(560 + k * 12);       // (o0 pair, o1 pair)
            ulonglong2 wb = ldc128(560 + k * 12 + 4);   // (o2 pair, (c2_0,c2_1))
            float2 c2p = unpack2(wb.y);
            float c22 = CW[560 + k * 12 + 8];
            accP0 = ffma2(v01, wa.x, accP0);
            accP1 = ffma2(v01, wa.y, accP1);
            accP2 = ffma2(v01, wb.x, accP2);
            a20 = fmaf(v2, c2p.x, a20);
            a21 = fmaf(v2, c2p.y, a21);
            a22 = fmaf(v2, c22, a22);
        }
        float2 r0 = unpack2(accP0), r1 = unpack2(accP1), r2 = unpack2(accP2);
        res[0] = r0.x + r0.y + a20 + CW[668];
        res[1] = r1.x + r1.y + a21 + CW[669];
        res[2] = r2.x + r2.y + a22 + CW[670];
    };

    float rA[3], rB[3];
    deform(offA, (float)iA,        rA);
    deform(offB, (float)iA + 1.f,  rB);

    const size_t plane = (size_t)HO * WO;
    size_t pa = (size_t)b * 3 * plane + (size_t)iA * WO + j;
    out[pa]             = rA[0];
    out[pa + plane]     = rA[1];
    out[pa + 2 * plane] = rA[2];
    pa += WO;
    out[pa]             = rB[0];
    out[pa + plane]     = rB[1];
    out[pa + 2 * plane] = rB[2];
}

extern "C" void kernel_launch(void* const* d_in, const int* in_sizes, int n_in,
                              void* d_out, int out_size)
{
    const float* x      = (const float*)d_in[0];
    const float* conv_w = (const float*)d_in[1];
    const float* conv_b = (const float*)d_in[2];
    const float* dcn_w  = (const float*)d_in[3];
    const float* dcn_b  = (const float*)d_in[4];
    float* out = (float*)d_out;

    float* sp = nullptr;  void* cp = nullptr;
    cudaGetSymbolAddress((void**)&sp, d_scratch);
    cudaGetSymbolAddress(&cp, CW);

    repack<<<1, 544>>>(conv_w, conv_b, dcn_w, dcn_b, sp);
    cudaMemcpyAsync(cp, sp, 672 * sizeof(float), cudaMemcpyDeviceToDevice);

    dim3 blk(32, 4);
    dim3 grd((WO + 31) / 32, (HO + 7) / 8, 16);
    dcn_fused<<<grd, blk>>>(x, out);
}